// round 5
// baseline (speedup 1.0000x reference)
#include <cuda_runtime.h>
#include <cuda_bf16.h>
#include <math.h>

// Problem constants
#define B_   64
#define L_   512
#define D_   256
#define H_   256
#define T_   11
#define M_   (B_ * L_)      // 32768 rows (b*L + l)
#define G4H  (4 * H_)       // 1024 gate rows (i,f,g,o blocks of 256)

#define NBLK_LSTM 128       // persistent blocks for the recurrence (<=148 SMs, 1/SM)

// ---------------------------------------------------------------------------
// Scratch (static __device__ — no allocations allowed)
// ---------------------------------------------------------------------------
__device__ float g_gates[2 * 32768 * 1024];     // [dir][b*L+l][4H] input-proj + bias
__device__ float g_hseq[32768 * 512];           // [b*L+l][512] = concat(hf, hb)
__device__ float g_hbuf[2][2][B_ * H_];         // [dir][parity][b*H + j] double-buffered h
__device__ float g_logits[32768 * T_];          // [b*L+l][T]
__device__ unsigned int g_bar_count;
__device__ unsigned int g_bar_gen;

// ---------------------------------------------------------------------------
// Init: copy h0 into parity-0 h buffers, reset grid barrier
// ---------------------------------------------------------------------------
__global__ void init_kernel(const float* __restrict__ h0) {
    int i = blockIdx.x * blockDim.x + threadIdx.x;
    if (i == 0) { g_bar_count = 0u; g_bar_gen = 0u; }
    if (i < 2 * B_ * H_) {
        int dir = i / (B_ * H_);
        int rem = i - dir * (B_ * H_);
        g_hbuf[dir][0][rem] = h0[i];
    }
}

// ---------------------------------------------------------------------------
// Fused embedding-gather + input GEMM:
//   g_gates[dir][m][n] = emb[sent[m]] . W_ih_dir[n] + b_dir[n]
// M=32768, N=1024, K=256.  64x64 tiles, 256 threads, 4x4 per thread.
// ---------------------------------------------------------------------------
__global__ __launch_bounds__(256) void input_gemm_kernel(
    const int* __restrict__ sent, const float* __restrict__ emb,
    const float* __restrict__ Wf, const float* __restrict__ bf,
    const float* __restrict__ Wb, const float* __restrict__ bb)
{
    __shared__ float As[16][68];
    __shared__ float Bs[16][68];
    __shared__ int   sidx[64];

    const int dir = blockIdx.z;
    const float* W    = dir ? Wb : Wf;
    const float* bias = dir ? bb : bf;
    float* out = g_gates + (size_t)dir * M_ * G4H;

    const int n0 = blockIdx.x * 64;
    const int m0 = blockIdx.y * 64;
    const int tid = threadIdx.x;

    if (tid < 64) sidx[tid] = sent[m0 + tid];
    __syncthreads();

    const int lrow = tid >> 2;          // 0..63
    const int lk   = (tid & 3) * 4;     // 0,4,8,12
    const int tx = tid & 15, ty = tid >> 4;

    float acc[4][4];
#pragma unroll
    for (int i = 0; i < 4; i++)
#pragma unroll
        for (int j = 0; j < 4; j++) acc[i][j] = 0.f;

    const float* arow = emb + (size_t)sidx[lrow] * D_ + lk;
    const float* brow = W   + (size_t)(n0 + lrow) * D_ + lk;

    for (int k0 = 0; k0 < D_; k0 += 16) {
        float4 a  = *(const float4*)(arow + k0);
        float4 bv = *(const float4*)(brow + k0);
        As[lk + 0][lrow] = a.x;  As[lk + 1][lrow] = a.y;
        As[lk + 2][lrow] = a.z;  As[lk + 3][lrow] = a.w;
        Bs[lk + 0][lrow] = bv.x; Bs[lk + 1][lrow] = bv.y;
        Bs[lk + 2][lrow] = bv.z; Bs[lk + 3][lrow] = bv.w;
        __syncthreads();
#pragma unroll
        for (int kk = 0; kk < 16; kk++) {
            float4 a4 = *(const float4*)&As[kk][ty * 4];
            float4 b4 = *(const float4*)&Bs[kk][tx * 4];
            float av[4] = {a4.x, a4.y, a4.z, a4.w};
            float bw[4] = {b4.x, b4.y, b4.z, b4.w};
#pragma unroll
            for (int i = 0; i < 4; i++)
#pragma unroll
                for (int j = 0; j < 4; j++)
                    acc[i][j] = fmaf(av[i], bw[j], acc[i][j]);
        }
        __syncthreads();
    }

#pragma unroll
    for (int i = 0; i < 4; i++) {
        int m = m0 + ty * 4 + i;
        int n = n0 + tx * 4;
        float4 o;
        o.x = acc[i][0] + bias[n + 0];
        o.y = acc[i][1] + bias[n + 1];
        o.z = acc[i][2] + bias[n + 2];
        o.w = acc[i][3] + bias[n + 3];
        *(float4*)&out[(size_t)m * G4H + n] = o;
    }
}

// ---------------------------------------------------------------------------
// Grid barrier (sense-reversing, all NBLK_LSTM blocks co-resident)
// ---------------------------------------------------------------------------
__device__ __forceinline__ void grid_barrier() {
    __syncthreads();
    if (threadIdx.x == 0) {
        __threadfence();
        unsigned gen = *((volatile unsigned*)&g_bar_gen);
        if (atomicAdd(&g_bar_count, 1u) == (NBLK_LSTM - 1u)) {
            g_bar_count = 0u;
            __threadfence();
            atomicAdd(&g_bar_gen, 1u);
        } else {
            while (*((volatile unsigned*)&g_bar_gen) == gen) { __nanosleep(40); }
        }
    }
    __syncthreads();
}

// ---------------------------------------------------------------------------
// Persistent BiLSTM recurrence.
// 128 blocks: dir = bid>>6; block owns 8 batches x 32 hidden units.
// W_hh slice (128 rows x 256) lives in smem for all 512 steps.
// ---------------------------------------------------------------------------
__global__ __launch_bounds__(256, 1) void lstm_kernel(
    const float* __restrict__ c0,
    const float* __restrict__ Whh_f, const float* __restrict__ Whh_b)
{
    extern __shared__ float sm[];
    float* Wsm = sm;                       // 128 rows * 260 floats (pad 4)
    float* hsm = sm + 128 * 260;           // 8 * 256
    float* Gsm = hsm + 8 * 256;            // 128 * 8

    const int tid = threadIdx.x;
    const int bid = blockIdx.x;
    const int dir = bid >> 6;
    const int sub = bid & 63;
    const int b0  = (sub >> 3) * 8;        // batch tile base
    const int j0  = (sub & 7) * 32;        // hidden tile base

    // Load W_hh slice once: row r -> gate g=r>>5, unit j0+(r&31)
    const float4* Wg4 = (const float4*)(dir ? Whh_b : Whh_f);
    float4* Wsm4 = (float4*)Wsm;
    for (int idx = tid; idx < 128 * 64; idx += 256) {
        int r = idx >> 6, k4 = idx & 63;
        int g = r >> 5, jj = r & 31;
        Wsm4[r * 65 + k4] = Wg4[(size_t)(g * H_ + j0 + jj) * 64 + k4];
    }

    // Per-thread cell state (consistent mapping each step)
    const int ub = tid >> 5, ujj = tid & 31;
    float c = c0[dir * B_ * H_ + (b0 + ub) * H_ + j0 + ujj];

    // GEMM thread mapping: 128 rows x 2 batch-quads
    const int r  = tid & 127;
    const int bq = tid >> 7;
    const int gg_ = r >> 5, jj_ = r & 31;
    const int grow = gg_ * H_ + j0 + jj_;
    const float* gatesD = g_gates + (size_t)dir * M_ * G4H;
    float4* hsm4 = (float4*)hsm;

    __syncthreads();

    for (int t = 0; t < L_; t++) {
        const int l  = dir ? (L_ - 1 - t) : t;
        const float* hread  = g_hbuf[dir][t & 1];
        float*       hwrite = g_hbuf[dir][(t & 1) ^ 1];

        // Stage previous h (all 256 units for our 8 batches); L2-coherent loads
        const float4* hr4 = (const float4*)hread;
        for (int i = tid; i < 8 * 64; i += 256) {
            int row = i >> 6, c4 = i & 63;
            hsm4[row * 64 + c4] = __ldcg(&hr4[(b0 + row) * 64 + c4]);
        }

        // Prefetch input-gate pre-activations for our 4 outputs
        float gi[4];
#pragma unroll
        for (int i = 0; i < 4; i++)
            gi[i] = gatesD[(size_t)((b0 + bq * 4 + i) * L_ + l) * G4H + grow];

        __syncthreads();

        float a0 = 0.f, a1 = 0.f, a2 = 0.f, a3 = 0.f;
#pragma unroll 4
        for (int k4 = 0; k4 < 64; k4++) {
            float4 w  = Wsm4[r * 65 + k4];
            float4 h0v = hsm4[(bq * 4 + 0) * 64 + k4];
            float4 h1v = hsm4[(bq * 4 + 1) * 64 + k4];
            float4 h2v = hsm4[(bq * 4 + 2) * 64 + k4];
            float4 h3v = hsm4[(bq * 4 + 3) * 64 + k4];
            a0 = fmaf(w.x, h0v.x, a0); a0 = fmaf(w.y, h0v.y, a0);
            a0 = fmaf(w.z, h0v.z, a0); a0 = fmaf(w.w, h0v.w, a0);
            a1 = fmaf(w.x, h1v.x, a1); a1 = fmaf(w.y, h1v.y, a1);
            a1 = fmaf(w.z, h1v.z, a1); a1 = fmaf(w.w, h1v.w, a1);
            a2 = fmaf(w.x, h2v.x, a2); a2 = fmaf(w.y, h2v.y, a2);
            a2 = fmaf(w.z, h2v.z, a2); a2 = fmaf(w.w, h2v.w, a2);
            a3 = fmaf(w.x, h3v.x, a3); a3 = fmaf(w.y, h3v.y, a3);
            a3 = fmaf(w.z, h3v.z, a3); a3 = fmaf(w.w, h3v.w, a3);
        }
        Gsm[r * 8 + bq * 4 + 0] = a0 + gi[0];
        Gsm[r * 8 + bq * 4 + 1] = a1 + gi[1];
        Gsm[r * 8 + bq * 4 + 2] = a2 + gi[2];
        Gsm[r * 8 + bq * 4 + 3] = a3 + gi[3];
        __syncthreads();

        // Gate nonlinearity + state update (PyTorch order i,f,g,o)
        float iv = Gsm[( 0 + ujj) * 8 + ub];
        float fv = Gsm[(32 + ujj) * 8 + ub];
        float gv = Gsm[(64 + ujj) * 8 + ub];
        float ov = Gsm[(96 + ujj) * 8 + ub];
        float si = 1.f / (1.f + expf(-iv));
        float sf = 1.f / (1.f + expf(-fv));
        float so = 1.f / (1.f + expf(-ov));
        c = sf * c + si * tanhf(gv);
        float h = so * tanhf(c);

        int bglob = b0 + ub;
        __stcg(&hwrite[bglob * H_ + j0 + ujj], h);
        __stcg(&g_hseq[(size_t)(bglob * L_ + l) * 512 + dir * H_ + j0 + ujj], h);

        grid_barrier();
    }
}

// ---------------------------------------------------------------------------
// Output projection: logits[m][t] = hseq[m] . W_out[t] + b_out[t]
// ---------------------------------------------------------------------------
__global__ __launch_bounds__(256) void logits_kernel(
    const float* __restrict__ Wout, const float* __restrict__ bout)
{
    __shared__ float Wo[T_ * 512];
    __shared__ float bo[T_];
    int tid = threadIdx.x;
    for (int i = tid; i < T_ * 512; i += 256) Wo[i] = Wout[i];
    if (tid < T_) bo[tid] = bout[tid];
    __syncthreads();

    int idx = blockIdx.x * 256 + tid;   // 0..32767
    const float4* h4 = (const float4*)(g_hseq + (size_t)idx * 512);
    float acc[T_];
#pragma unroll
    for (int t = 0; t < T_; t++) acc[t] = 0.f;

    for (int k4 = 0; k4 < 128; k4++) {
        float4 h = h4[k4];
#pragma unroll
        for (int t = 0; t < T_; t++) {
            float4 w = *(const float4*)&Wo[t * 512 + k4 * 4];
            acc[t] = fmaf(h.x, w.x, fmaf(h.y, w.y, fmaf(h.z, w.z, fmaf(h.w, w.w, acc[t]))));
        }
    }
#pragma unroll
    for (int t = 0; t < T_; t++)
        g_logits[(size_t)idx * T_ + t] = acc[t] + bo[t];
}

// ---------------------------------------------------------------------------
// Viterbi: one block (1 warp) per batch. First-index argmax (strict >) to
// match jnp.argmax tie-breaking. Backpointers kept in smem.
// ---------------------------------------------------------------------------
__global__ __launch_bounds__(32) void viterbi_kernel(
    const float* __restrict__ trans, float* scores, float* paths)
{
    __shared__ float tr[T_ * T_];
    __shared__ float prev[T_];
    __shared__ unsigned char bps[(L_ - 1) * T_];

    int b = blockIdx.x;
    int j = threadIdx.x;

    for (int i = j; i < T_ * T_; i += 32) tr[i] = trans[i];
    if (j < T_) prev[j] = g_logits[(size_t)(b * L_) * T_ + j];
    __syncwarp();

    for (int t = 1; t < L_; t++) {
        float best = 0.f; int bp = 0;
        if (j < T_) {
            best = prev[0] + tr[j];
            bp = 0;
#pragma unroll
            for (int i = 1; i < T_; i++) {
                float v = prev[i] + tr[i * T_ + j];
                if (v > best) { best = v; bp = i; }
            }
        }
        __syncwarp();
        if (j < T_) {
            prev[j] = g_logits[(size_t)(b * L_ + t) * T_ + j] + best;
            bps[(t - 1) * T_ + j] = (unsigned char)bp;
        }
        __syncwarp();
    }

    if (j == 0) {
        float best = prev[0]; int tag = 0;
        for (int i = 1; i < T_; i++) if (prev[i] > best) { best = prev[i]; tag = i; }
        if (scores) scores[b] = best;
        if (paths) {
            paths[b * L_ + (L_ - 1)] = (float)tag;
            int st = tag;
            for (int t = L_ - 2; t >= 0; t--) {
                st = bps[t * T_ + st];
                paths[b * L_ + t] = (float)st;
            }
        }
    }
}

// ---------------------------------------------------------------------------
// Launcher
// ---------------------------------------------------------------------------
extern "C" void kernel_launch(void* const* d_in, const int* in_sizes, int n_in,
                              void* d_out, int out_size)
{
    const int*   sent  = (const int*)  d_in[0];
    const float* emb   = (const float*)d_in[1];
    const float* Wih_f = (const float*)d_in[2];
    const float* Whh_f = (const float*)d_in[3];
    const float* b_f   = (const float*)d_in[4];
    const float* Wih_b = (const float*)d_in[5];
    const float* Whh_b = (const float*)d_in[6];
    const float* b_b   = (const float*)d_in[7];
    const float* Wout  = (const float*)d_in[8];
    const float* bout  = (const float*)d_in[9];
    const float* trans = (const float*)d_in[10];
    const float* h0    = (const float*)d_in[11];
    const float* c0    = (const float*)d_in[12];

    float* out = (float*)d_out;
    float* scores = nullptr;
    float* paths  = nullptr;
    if (out_size >= B_ + B_ * L_)      { scores = out; paths = out + B_; }
    else if (out_size == B_ * L_)      { paths = out; }
    else                               { scores = out; }

    // 1. init h buffers + barrier
    init_kernel<<<128, 256>>>(h0);

    // 2. fused embed + input projections (both directions)
    dim3 gg(G4H / 64, M_ / 64, 2);   // (16, 512, 2)
    input_gemm_kernel<<<gg, 256>>>(sent, emb, Wih_f, b_f, Wih_b, b_b);

    // 3. persistent recurrence (128 co-resident blocks, 142 KB smem each)
    const int smem_bytes = (128 * 260 + 8 * 256 + 128 * 8) * (int)sizeof(float);
    cudaFuncSetAttribute(lstm_kernel, cudaFuncAttributeMaxDynamicSharedMemorySize, smem_bytes);
    lstm_kernel<<<NBLK_LSTM, 256, smem_bytes>>>(c0, Whh_f, Whh_b);

    // 4. output projection
    logits_kernel<<<M_ / 256, 256>>>(Wout, bout);

    // 5. Viterbi decode + write outputs
    viterbi_kernel<<<B_, 32>>>(trans, scores, paths);
}

// round 6
// speedup vs baseline: 1.1944x; 1.1944x over previous
#include <cuda_runtime.h>
#include <cuda_bf16.h>
#include <math.h>

// Problem constants
#define B_   64
#define L_   512
#define D_   256
#define H_   256
#define T_   11
#define M_   (B_ * L_)      // 32768 rows (b*L + l)
#define G4H  (4 * H_)       // 1024 gate rows (i,f,g,o blocks of 256)

#define NBLK_LSTM 128       // persistent blocks (<=148 SMs, 1/SM)
#define NBLK_DIR  64        // blocks per direction (barrier group)

// ---------------------------------------------------------------------------
// Scratch (static __device__ — no allocations allowed)
// ---------------------------------------------------------------------------
__device__ float g_gates[2 * 32768 * 1024];     // [dir][b*L+l][4H] input-proj + bias
__device__ float g_hseq[32768 * 512];           // [b*L+l][512] = concat(hf, hb)
__device__ float g_hbuf[2][2][B_ * H_];         // [dir][parity][b*H + j]
__device__ float g_logits[32768 * T_];          // [b*L+l][T]
__device__ unsigned int g_bar_count[2];
__device__ unsigned int g_bar_gen[2];

// ---------------------------------------------------------------------------
// Init: copy h0 into parity-0 h buffers, reset grid barriers
// ---------------------------------------------------------------------------
__global__ void init_kernel(const float* __restrict__ h0) {
    int i = blockIdx.x * blockDim.x + threadIdx.x;
    if (i < 2) { g_bar_count[i] = 0u; g_bar_gen[i] = 0u; }
    if (i < 2 * B_ * H_) {
        int dir = i / (B_ * H_);
        int rem = i - dir * (B_ * H_);
        g_hbuf[dir][0][rem] = h0[i];
    }
}

// ---------------------------------------------------------------------------
// Fused embedding-gather + input GEMM:
//   g_gates[dir][m][n] = emb[sent[m]] . W_ih_dir[n] + b_dir[n]
// M=32768, N=1024, K=256.  64x64 tiles, 256 threads, 4x4 per thread.
// ---------------------------------------------------------------------------
__global__ __launch_bounds__(256) void input_gemm_kernel(
    const int* __restrict__ sent, const float* __restrict__ emb,
    const float* __restrict__ Wf, const float* __restrict__ bf,
    const float* __restrict__ Wb, const float* __restrict__ bb)
{
    __shared__ float As[16][68];
    __shared__ float Bs[16][68];
    __shared__ int   sidx[64];

    const int dir = blockIdx.z;
    const float* W    = dir ? Wb : Wf;
    const float* bias = dir ? bb : bf;
    float* out = g_gates + (size_t)dir * M_ * G4H;

    const int n0 = blockIdx.x * 64;
    const int m0 = blockIdx.y * 64;
    const int tid = threadIdx.x;

    if (tid < 64) sidx[tid] = sent[m0 + tid];
    __syncthreads();

    const int lrow = tid >> 2;          // 0..63
    const int lk   = (tid & 3) * 4;     // 0,4,8,12
    const int tx = tid & 15, ty = tid >> 4;

    float acc[4][4];
#pragma unroll
    for (int i = 0; i < 4; i++)
#pragma unroll
        for (int j = 0; j < 4; j++) acc[i][j] = 0.f;

    const float* arow = emb + (size_t)sidx[lrow] * D_ + lk;
    const float* brow = W   + (size_t)(n0 + lrow) * D_ + lk;

    for (int k0 = 0; k0 < D_; k0 += 16) {
        float4 a  = *(const float4*)(arow + k0);
        float4 bv = *(const float4*)(brow + k0);
        As[lk + 0][lrow] = a.x;  As[lk + 1][lrow] = a.y;
        As[lk + 2][lrow] = a.z;  As[lk + 3][lrow] = a.w;
        Bs[lk + 0][lrow] = bv.x; Bs[lk + 1][lrow] = bv.y;
        Bs[lk + 2][lrow] = bv.z; Bs[lk + 3][lrow] = bv.w;
        __syncthreads();
#pragma unroll
        for (int kk = 0; kk < 16; kk++) {
            float4 a4 = *(const float4*)&As[kk][ty * 4];
            float4 b4 = *(const float4*)&Bs[kk][tx * 4];
            float av[4] = {a4.x, a4.y, a4.z, a4.w};
            float bw[4] = {b4.x, b4.y, b4.z, b4.w};
#pragma unroll
            for (int i = 0; i < 4; i++)
#pragma unroll
                for (int j = 0; j < 4; j++)
                    acc[i][j] = fmaf(av[i], bw[j], acc[i][j]);
        }
        __syncthreads();
    }

#pragma unroll
    for (int i = 0; i < 4; i++) {
        int m = m0 + ty * 4 + i;
        int n = n0 + tx * 4;
        float4 o;
        o.x = acc[i][0] + bias[n + 0];
        o.y = acc[i][1] + bias[n + 1];
        o.z = acc[i][2] + bias[n + 2];
        o.w = acc[i][3] + bias[n + 3];
        *(float4*)&out[(size_t)m * G4H + n] = o;
    }
}

// ---------------------------------------------------------------------------
// Per-direction grid barrier (sense-reversing, 64 co-resident blocks)
// ---------------------------------------------------------------------------
__device__ __forceinline__ void grid_barrier(int dir) {
    __syncthreads();
    if (threadIdx.x == 0) {
        __threadfence();
        unsigned gen = *((volatile unsigned*)&g_bar_gen[dir]);
        if (atomicAdd(&g_bar_count[dir], 1u) == (NBLK_DIR - 1u)) {
            g_bar_count[dir] = 0u;
            __threadfence();
            atomicAdd(&g_bar_gen[dir], 1u);
        } else {
            while (*((volatile unsigned*)&g_bar_gen[dir]) == gen) { __nanosleep(20); }
        }
    }
    __syncthreads();
}

// ---------------------------------------------------------------------------
// Persistent BiLSTM recurrence.
// 128 blocks: dir = bid>>6; block owns 8 batches x 32 hidden units
// (= 128 gate rows). W_hh slice (128x256) lives in smem for all 512 steps.
//
// GEMM thread layout (256 thr): ks = tid&7 (interleaved k-split),
// tile = tid>>3: rt = tile>>1 (8-row group), bq = tile&1 (4-batch group).
// Each thread: 8 rows x 4 batches x 32 k  -> 1024 FMA, 96 LDS.128.
// K-split reduced with 3 warp-shuffle butterfly rounds (lanes differ in ks).
// ---------------------------------------------------------------------------
__global__ __launch_bounds__(256, 1) void lstm_kernel(
    const float* __restrict__ c0,
    const float* __restrict__ Whh_f, const float* __restrict__ Whh_b)
{
    extern __shared__ float sm[];
    float4* Wsm4 = (float4*)sm;                    // 128 rows * 65 float4 (pad)
    float4* hsm4 = (float4*)(sm + 128 * 260);      // 8 batches * 65 float4
    float*  Gsm  = sm + 128 * 260 + 8 * 260;       // 128 rows * 9 (pad)

    const int tid = threadIdx.x;
    const int bid = blockIdx.x;
    const int dir = bid >> 6;
    const int sub = bid & 63;
    const int b0  = (sub >> 3) * 8;        // batch tile base
    const int j0  = (sub & 7) * 32;        // hidden tile base

    // Load W_hh slice once: smem row r -> gate g=r>>5, unit j0+(r&31)
    const float4* Wg4 = (const float4*)(dir ? Whh_b : Whh_f);
    for (int idx = tid; idx < 128 * 64; idx += 256) {
        int r = idx >> 6, k4 = idx & 63;
        int g = r >> 5, jj = r & 31;
        Wsm4[r * 65 + k4] = Wg4[(size_t)(g * H_ + j0 + jj) * 64 + k4];
    }

    // Cell-update thread mapping (consistent each step)
    const int ub = tid >> 5, ujj = tid & 31;
    float c = c0[dir * B_ * H_ + (b0 + ub) * H_ + j0 + ujj];

    // GEMM thread mapping
    const int ks   = tid & 7;
    const int tile = tid >> 3;
    const int rt   = tile >> 1;            // 0..15 -> rows rt*8..rt*8+7
    const int bq   = tile & 1;             // batches bq*4..bq*4+3
    // After reduction this lane owns row rt*8 + brev3(ks), batches bq*4+0..3
    const int ri_fin = ((ks & 1) << 2) | (ks & 2) | ((ks >> 2) & 1);
    const int row_fin = rt * 8 + ri_fin;
    const int grow_fin = (row_fin >> 5) * H_ + j0 + (row_fin & 31);

    const float* gatesD = g_gates + (size_t)dir * M_ * G4H;

    __syncthreads();

    for (int t = 0; t < L_; t++) {
        const int l  = dir ? (L_ - 1 - t) : t;
        const float* hread  = g_hbuf[dir][t & 1];
        float*       hwrite = g_hbuf[dir][(t & 1) ^ 1];

        // Stage previous h (8 batches x 256 units); L2-coherent loads
        const float4* hr4 = (const float4*)hread;
        for (int i = tid; i < 8 * 64; i += 256) {
            int r = i >> 6, c4 = i & 63;
            hsm4[r * 65 + c4] = __ldcg(&hr4[(b0 + r) * 64 + c4]);
        }

        // Prefetch input-projection preacts for this lane's final outputs
        float gi[4];
#pragma unroll
        for (int bi = 0; bi < 4; bi++)
            gi[bi] = gatesD[(size_t)((b0 + bq * 4 + bi) * L_ + l) * G4H + grow_fin];

        __syncthreads();

        // 8x4 register-tiled GEMM, interleaved k-split (k4 = ks + 8*kk)
        float acc[32];
#pragma unroll
        for (int v = 0; v < 32; v++) acc[v] = 0.f;

#pragma unroll 2
        for (int kk = 0; kk < 8; kk++) {
            const int k4 = ks + kk * 8;
            float4 hv[4];
#pragma unroll
            for (int bi = 0; bi < 4; bi++)
                hv[bi] = hsm4[(bq * 4 + bi) * 65 + k4];
#pragma unroll
            for (int ri = 0; ri < 8; ri++) {
                float4 w = Wsm4[(rt * 8 + ri) * 65 + k4];
#pragma unroll
                for (int bi = 0; bi < 4; bi++) {
                    float a = acc[ri * 4 + bi];
                    a = fmaf(w.x, hv[bi].x, a);
                    a = fmaf(w.y, hv[bi].y, a);
                    a = fmaf(w.z, hv[bi].z, a);
                    a = fmaf(w.w, hv[bi].w, a);
                    acc[ri * 4 + bi] = a;
                }
            }
        }

        // K-split reduction: 3 butterfly rounds over lane bits 0..2 (ks).
        // Branch-free (selects), static indices -> stays in registers.
#pragma unroll
        for (int s = 0; s < 3; s++) {
            const int half = 16 >> s;              // 16, 8, 4
            const bool up = (ks >> s) & 1;
#pragma unroll
            for (int i = 0; i < half; i++) {
                float send = up ? acc[i] : acc[i + half];
                float recv = __shfl_xor_sync(0xffffffffu, send, 1 << s);
                acc[i] = (up ? acc[i + half] : acc[i]) + recv;
            }
        }
        // Lane now holds 4 finals: row = row_fin, batches bq*4 + (0..3)
#pragma unroll
        for (int bi = 0; bi < 4; bi++)
            Gsm[row_fin * 9 + bq * 4 + bi] = acc[bi] + gi[bi];
        __syncthreads();

        // Gate nonlinearity + state update (PyTorch order i,f,g,o)
        float iv = Gsm[( 0 + ujj) * 9 + ub];
        float fv = Gsm[(32 + ujj) * 9 + ub];
        float gv = Gsm[(64 + ujj) * 9 + ub];
        float ov = Gsm[(96 + ujj) * 9 + ub];
        float si = 1.f / (1.f + expf(-iv));
        float sf = 1.f / (1.f + expf(-fv));
        float so = 1.f / (1.f + expf(-ov));
        c = sf * c + si * tanhf(gv);
        float h = so * tanhf(c);

        int bglob = b0 + ub;
        __stcg(&hwrite[bglob * H_ + j0 + ujj], h);
        __stcg(&g_hseq[(size_t)(bglob * L_ + l) * 512 + dir * H_ + j0 + ujj], h);

        grid_barrier(dir);
    }
}

// ---------------------------------------------------------------------------
// Output projection: logits[m][t] = hseq[m] . W_out[t] + b_out[t]
// ---------------------------------------------------------------------------
__global__ __launch_bounds__(256) void logits_kernel(
    const float* __restrict__ Wout, const float* __restrict__ bout)
{
    __shared__ float Wo[T_ * 512];
    __shared__ float bo[T_];
    int tid = threadIdx.x;
    for (int i = tid; i < T_ * 512; i += 256) Wo[i] = Wout[i];
    if (tid < T_) bo[tid] = bout[tid];
    __syncthreads();

    int idx = blockIdx.x * 256 + tid;   // 0..32767
    const float4* h4 = (const float4*)(g_hseq + (size_t)idx * 512);
    float acc[T_];
#pragma unroll
    for (int t = 0; t < T_; t++) acc[t] = 0.f;

    for (int k4 = 0; k4 < 128; k4++) {
        float4 h = h4[k4];
#pragma unroll
        for (int t = 0; t < T_; t++) {
            float4 w = *(const float4*)&Wo[t * 512 + k4 * 4];
            acc[t] = fmaf(h.x, w.x, fmaf(h.y, w.y, fmaf(h.z, w.z, fmaf(h.w, w.w, acc[t]))));
        }
    }
#pragma unroll
    for (int t = 0; t < T_; t++)
        g_logits[(size_t)idx * T_ + t] = acc[t] + bo[t];
}

// ---------------------------------------------------------------------------
// Viterbi: one warp per batch. First-index argmax (strict >) matches
// jnp.argmax tie-breaking. Backpointers in smem.
// ---------------------------------------------------------------------------
__global__ __launch_bounds__(32) void viterbi_kernel(
    const float* __restrict__ trans, float* scores, float* paths)
{
    __shared__ float tr[T_ * T_];
    __shared__ float prev[T_];
    __shared__ unsigned char bps[(L_ - 1) * T_];

    int b = blockIdx.x;
    int j = threadIdx.x;

    for (int i = j; i < T_ * T_; i += 32) tr[i] = trans[i];
    if (j < T_) prev[j] = g_logits[(size_t)(b * L_) * T_ + j];
    __syncwarp();

    for (int t = 1; t < L_; t++) {
        float best = 0.f; int bp = 0;
        if (j < T_) {
            best = prev[0] + tr[j];
            bp = 0;
#pragma unroll
            for (int i = 1; i < T_; i++) {
                float v = prev[i] + tr[i * T_ + j];
                if (v > best) { best = v; bp = i; }
            }
        }
        __syncwarp();
        if (j < T_) {
            prev[j] = g_logits[(size_t)(b * L_ + t) * T_ + j] + best;
            bps[(t - 1) * T_ + j] = (unsigned char)bp;
        }
        __syncwarp();
    }

    if (j == 0) {
        float best = prev[0]; int tag = 0;
        for (int i = 1; i < T_; i++) if (prev[i] > best) { best = prev[i]; tag = i; }
        if (scores) scores[b] = best;
        if (paths) {
            paths[b * L_ + (L_ - 1)] = (float)tag;
            int st = tag;
            for (int t = L_ - 2; t >= 0; t--) {
                st = bps[t * T_ + st];
                paths[b * L_ + t] = (float)st;
            }
        }
    }
}

// ---------------------------------------------------------------------------
// Launcher
// ---------------------------------------------------------------------------
extern "C" void kernel_launch(void* const* d_in, const int* in_sizes, int n_in,
                              void* d_out, int out_size)
{
    const int*   sent  = (const int*)  d_in[0];
    const float* emb   = (const float*)d_in[1];
    const float* Wih_f = (const float*)d_in[2];
    const float* Whh_f = (const float*)d_in[3];
    const float* b_f   = (const float*)d_in[4];
    const float* Wih_b = (const float*)d_in[5];
    const float* Whh_b = (const float*)d_in[6];
    const float* b_b   = (const float*)d_in[7];
    const float* Wout  = (const float*)d_in[8];
    const float* bout  = (const float*)d_in[9];
    const float* trans = (const float*)d_in[10];
    const float* h0    = (const float*)d_in[11];
    const float* c0    = (const float*)d_in[12];

    float* out = (float*)d_out;
    float* scores = nullptr;
    float* paths  = nullptr;
    if (out_size >= B_ + B_ * L_)      { scores = out; paths = out + B_; }
    else if (out_size == B_ * L_)      { paths = out; }
    else                               { scores = out; }

    // 1. init h buffers + barriers
    init_kernel<<<128, 256>>>(h0);

    // 2. fused embed + input projections (both directions)
    dim3 gg(G4H / 64, M_ / 64, 2);   // (16, 512, 2)
    input_gemm_kernel<<<gg, 256>>>(sent, emb, Wih_f, b_f, Wih_b, b_b);

    // 3. persistent recurrence (128 co-resident blocks, ~143 KB smem each)
    const int smem_bytes = (128 * 260 + 8 * 260 + 128 * 9) * (int)sizeof(float);
    cudaFuncSetAttribute(lstm_kernel, cudaFuncAttributeMaxDynamicSharedMemorySize, smem_bytes);
    lstm_kernel<<<NBLK_LSTM, 256, smem_bytes>>>(c0, Whh_f, Whh_b);

    // 4. output projection
    logits_kernel<<<M_ / 256, 256>>>(Wout, bout);

    // 5. Viterbi decode + write outputs
    viterbi_kernel<<<B_, 32>>>(trans, scores, paths);
}

// round 7
// speedup vs baseline: 1.4414x; 1.2068x over previous
#include <cuda_runtime.h>
#include <cuda_bf16.h>
#include <math.h>

// Problem constants
#define B_   64
#define L_   512
#define D_   256
#define H_   256
#define T_   11
#define M_   (B_ * L_)      // 32768 rows (b*L + l)
#define G4H  (4 * H_)       // 1024 gate rows (i,f,g,o blocks of 256)

#define NBLK_LSTM 128       // persistent blocks (<=148 SMs, 1/SM)

// ---------------------------------------------------------------------------
// Scratch (static __device__ — no allocations allowed)
// ---------------------------------------------------------------------------
__device__ float g_gates[2 * 32768 * 1024];     // [dir][b*L+l][4H] input-proj + bias
__device__ float g_hseq[32768 * 512];           // [b*L+l][512] = concat(hf, hb)
__device__ float g_hbuf[2][2][B_ * H_];         // [dir][parity][b*H + j]
__device__ float g_logits[32768 * T_];          // [b*L+l][T]
__device__ unsigned int g_cnt[2][8];            // per-(dir, batch-group) completion count

// ---------------------------------------------------------------------------
// Init: copy h0 into parity-0 h buffers, reset counters
// ---------------------------------------------------------------------------
__global__ void init_kernel(const float* __restrict__ h0) {
    int i = blockIdx.x * blockDim.x + threadIdx.x;
    if (i < 16) ((unsigned int*)g_cnt)[i] = 0u;
    if (i < 2 * B_ * H_) {
        int dir = i / (B_ * H_);
        int rem = i - dir * (B_ * H_);
        g_hbuf[dir][0][rem] = h0[i];
    }
}

// ---------------------------------------------------------------------------
// Fused embedding-gather + input GEMM:
//   g_gates[dir][m][n] = emb[sent[m]] . W_ih_dir[n] + b_dir[n]
// M=32768, N=1024, K=256.
// 128x64 block tile, 256 threads, 8x4 per thread, k-chunk 16,
// double-buffered smem (A stored k-major for broadcast frag loads).
// ---------------------------------------------------------------------------
__global__ __launch_bounds__(256) void input_gemm_kernel(
    const int* __restrict__ sent, const float* __restrict__ emb,
    const float* __restrict__ Wf, const float* __restrict__ bf,
    const float* __restrict__ Wb, const float* __restrict__ bb)
{
    __shared__ float As[2][16][132];   // [buf][k][m]
    __shared__ float Bs[2][16][68];    // [buf][k][n]
    __shared__ int   sidx[128];

    const int dir = blockIdx.z;
    const float* W    = dir ? Wb : Wf;
    const float* bias = dir ? bb : bf;
    float* out = g_gates + (size_t)dir * M_ * G4H;

    const int n0 = blockIdx.x * 64;
    const int m0 = blockIdx.y * 128;
    const int tid = threadIdx.x;

    if (tid < 128) sidx[tid] = sent[m0 + tid];
    __syncthreads();

    // Global-load mapping
    const int rowA = tid >> 1;              // 0..127
    const int kA0  = (tid & 1) * 8;         // 0 or 8 (loads kA0..kA0+7)
    const int rowB = tid >> 2;              // 0..63
    const int kB0  = (tid & 3) * 4;         // 0,4,8,12
    const float* aBase = emb + (size_t)sidx[rowA] * D_ + kA0;
    const float* bBase = W   + (size_t)(n0 + rowB) * D_ + kB0;

    // Compute mapping: 8 rows x 4 cols per thread
    const int txn = tid & 15;               // n-quad 0..15
    const int tym = tid >> 4;               // m-oct 0..15

    float acc[8][4];
#pragma unroll
    for (int i = 0; i < 8; i++)
#pragma unroll
        for (int j = 0; j < 4; j++) acc[i][j] = 0.f;

    float4 pa0, pa1, pb;

    // Preload chunk 0 into buf 0
    pa0 = *(const float4*)(aBase + 0);
    pa1 = *(const float4*)(aBase + 4);
    pb  = *(const float4*)(bBase + 0);
    As[0][kA0 + 0][rowA] = pa0.x; As[0][kA0 + 1][rowA] = pa0.y;
    As[0][kA0 + 2][rowA] = pa0.z; As[0][kA0 + 3][rowA] = pa0.w;
    As[0][kA0 + 4][rowA] = pa1.x; As[0][kA0 + 5][rowA] = pa1.y;
    As[0][kA0 + 6][rowA] = pa1.z; As[0][kA0 + 7][rowA] = pa1.w;
    Bs[0][kB0 + 0][rowB] = pb.x;  Bs[0][kB0 + 1][rowB] = pb.y;
    Bs[0][kB0 + 2][rowB] = pb.z;  Bs[0][kB0 + 3][rowB] = pb.w;
    __syncthreads();

    for (int c = 0; c < 16; c++) {
        const int cur = c & 1;
        if (c < 15) {                       // prefetch next chunk into regs
            const float* ap = aBase + (c + 1) * 16;
            const float* bp = bBase + (c + 1) * 16;
            pa0 = *(const float4*)(ap + 0);
            pa1 = *(const float4*)(ap + 4);
            pb  = *(const float4*)(bp + 0);
        }
#pragma unroll
        for (int kk = 0; kk < 16; kk++) {
            float4 a0 = *(const float4*)&As[cur][kk][tym * 8];
            float4 a1 = *(const float4*)&As[cur][kk][tym * 8 + 4];
            float4 b  = *(const float4*)&Bs[cur][kk][txn * 4];
            float av[8] = {a0.x, a0.y, a0.z, a0.w, a1.x, a1.y, a1.z, a1.w};
            float bw[4] = {b.x, b.y, b.z, b.w};
#pragma unroll
            for (int i = 0; i < 8; i++)
#pragma unroll
                for (int j = 0; j < 4; j++)
                    acc[i][j] = fmaf(av[i], bw[j], acc[i][j]);
        }
        if (c < 15) {
            const int nxt = cur ^ 1;
            As[nxt][kA0 + 0][rowA] = pa0.x; As[nxt][kA0 + 1][rowA] = pa0.y;
            As[nxt][kA0 + 2][rowA] = pa0.z; As[nxt][kA0 + 3][rowA] = pa0.w;
            As[nxt][kA0 + 4][rowA] = pa1.x; As[nxt][kA0 + 5][rowA] = pa1.y;
            As[nxt][kA0 + 6][rowA] = pa1.z; As[nxt][kA0 + 7][rowA] = pa1.w;
            Bs[nxt][kB0 + 0][rowB] = pb.x;  Bs[nxt][kB0 + 1][rowB] = pb.y;
            Bs[nxt][kB0 + 2][rowB] = pb.z;  Bs[nxt][kB0 + 3][rowB] = pb.w;
        }
        __syncthreads();
    }

    const int nbase = n0 + txn * 4;
    float4 bv = *(const float4*)&bias[nbase];
#pragma unroll
    for (int i = 0; i < 8; i++) {
        int m = m0 + tym * 8 + i;
        float4 o;
        o.x = acc[i][0] + bv.x;
        o.y = acc[i][1] + bv.y;
        o.z = acc[i][2] + bv.z;
        o.w = acc[i][3] + bv.w;
        *(float4*)&out[(size_t)m * G4H + nbase] = o;
    }
}

// ---------------------------------------------------------------------------
// Persistent BiLSTM recurrence.
// 128 blocks: dir = bid>>6; block owns 8 batches (bg) x 32 hidden units (j0).
// Sync: per-(dir,bg) monotonic counter; consumer needs only its 8 producers.
// ---------------------------------------------------------------------------
__global__ __launch_bounds__(256, 1) void lstm_kernel(
    const float* __restrict__ c0,
    const float* __restrict__ Whh_f, const float* __restrict__ Whh_b)
{
    extern __shared__ float sm[];
    float4* Wsm4 = (float4*)sm;                    // 128 rows * 65 float4 (pad)
    float4* hsm4 = (float4*)(sm + 128 * 260);      // 8 batches * 65 float4
    float*  Gsm  = sm + 128 * 260 + 8 * 260;       // 128 rows * 9 (pad)

    const int tid = threadIdx.x;
    const int bid = blockIdx.x;
    const int dir = bid >> 6;
    const int sub = bid & 63;
    const int bg  = sub >> 3;              // batch group 0..7
    const int b0  = bg * 8;                // batch tile base
    const int j0  = (sub & 7) * 32;        // hidden tile base

    // Load W_hh slice once: smem row r -> gate g=r>>5, unit j0+(r&31)
    const float4* Wg4 = (const float4*)(dir ? Whh_b : Whh_f);
    for (int idx = tid; idx < 128 * 64; idx += 256) {
        int r = idx >> 6, k4 = idx & 63;
        int g = r >> 5, jj = r & 31;
        Wsm4[r * 65 + k4] = Wg4[(size_t)(g * H_ + j0 + jj) * 64 + k4];
    }

    // Cell-update thread mapping
    const int ub = tid >> 5, ujj = tid & 31;
    float c = c0[dir * B_ * H_ + (b0 + ub) * H_ + j0 + ujj];

    // GEMM thread mapping
    const int ks   = tid & 7;
    const int tile = tid >> 3;
    const int rt   = tile >> 1;            // 0..15 -> rows rt*8..rt*8+7
    const int bq   = tile & 1;             // batches bq*4..bq*4+3
    const int ri_fin = ((ks & 1) << 2) | (ks & 2) | ((ks >> 2) & 1);
    const int row_fin = rt * 8 + ri_fin;
    const int grow_fin = (row_fin >> 5) * H_ + j0 + (row_fin & 31);

    const float* gatesD = g_gates + (size_t)dir * M_ * G4H;
    volatile unsigned int* cnt = &g_cnt[dir][bg];

    __syncthreads();

    for (int t = 0; t < L_; t++) {
        const int l  = dir ? (L_ - 1 - t) : t;
        const float* hread  = g_hbuf[dir][t & 1];
        float*       hwrite = g_hbuf[dir][(t & 1) ^ 1];

        // Prefetch input-projection preacts (independent of h) — in flight
        // while we wait on producers.
        float gi[4];
#pragma unroll
        for (int bi = 0; bi < 4; bi++)
            gi[bi] = gatesD[(size_t)((b0 + bq * 4 + bi) * L_ + l) * G4H + grow_fin];

        // Wait for the 8 producers of this batch group (prev step published)
        if (t > 0) {
            const unsigned int need = 8u * (unsigned)t;
            while (*cnt < need) { __nanosleep(20); }
        }

        // Stage previous h (8 batches x 256 units); L2-coherent loads
        const float4* hr4 = (const float4*)hread;
        for (int i = tid; i < 8 * 64; i += 256) {
            int r = i >> 6, c4 = i & 63;
            hsm4[r * 65 + c4] = __ldcg(&hr4[(b0 + r) * 64 + c4]);
        }
        __syncthreads();

        // 8x4 register-tiled GEMM, interleaved k-split (k4 = ks + 8*kk)
        float acc[32];
#pragma unroll
        for (int v = 0; v < 32; v++) acc[v] = 0.f;

#pragma unroll 2
        for (int kk = 0; kk < 8; kk++) {
            const int k4 = ks + kk * 8;
            float4 hv[4];
#pragma unroll
            for (int bi = 0; bi < 4; bi++)
                hv[bi] = hsm4[(bq * 4 + bi) * 65 + k4];
#pragma unroll
            for (int ri = 0; ri < 8; ri++) {
                float4 w = Wsm4[(rt * 8 + ri) * 65 + k4];
#pragma unroll
                for (int bi = 0; bi < 4; bi++) {
                    float a = acc[ri * 4 + bi];
                    a = fmaf(w.x, hv[bi].x, a);
                    a = fmaf(w.y, hv[bi].y, a);
                    a = fmaf(w.z, hv[bi].z, a);
                    a = fmaf(w.w, hv[bi].w, a);
                    acc[ri * 4 + bi] = a;
                }
            }
        }

        // K-split reduction: 3 butterfly rounds over lane bits 0..2 (ks)
#pragma unroll
        for (int s = 0; s < 3; s++) {
            const int half = 16 >> s;              // 16, 8, 4
            const bool up = (ks >> s) & 1;
#pragma unroll
            for (int i = 0; i < half; i++) {
                float send = up ? acc[i] : acc[i + half];
                float recv = __shfl_xor_sync(0xffffffffu, send, 1 << s);
                acc[i] = (up ? acc[i + half] : acc[i]) + recv;
            }
        }
#pragma unroll
        for (int bi = 0; bi < 4; bi++)
            Gsm[row_fin * 9 + bq * 4 + bi] = acc[bi] + gi[bi];
        __syncthreads();

        // Gate nonlinearity + state update (PyTorch order i,f,g,o)
        float iv = Gsm[( 0 + ujj) * 9 + ub];
        float fv = Gsm[(32 + ujj) * 9 + ub];
        float gv = Gsm[(64 + ujj) * 9 + ub];
        float ov = Gsm[(96 + ujj) * 9 + ub];
        float si = 1.f / (1.f + expf(-iv));
        float sf = 1.f / (1.f + expf(-fv));
        float so = 1.f / (1.f + expf(-ov));
        c = sf * c + si * tanhf(gv);
        float h = so * tanhf(c);

        int bglob = b0 + ub;
        __stcg(&hwrite[bglob * H_ + j0 + ujj], h);
        __stcg(&g_hseq[(size_t)(bglob * L_ + l) * 512 + dir * H_ + j0 + ujj], h);

        // Publish: all h stores done -> bump group counter
        __syncthreads();
        if (tid == 0) {
            __threadfence();
            atomicAdd(&g_cnt[dir][bg], 1u);
        }
    }
}

// ---------------------------------------------------------------------------
// Output projection: logits[m][t] = hseq[m] . W_out[t] + b_out[t]
// Split-k x2: lane pairs share one m; shfl-xor combine.
// ---------------------------------------------------------------------------
__global__ __launch_bounds__(256) void logits_kernel(
    const float* __restrict__ Wout, const float* __restrict__ bout)
{
    __shared__ float Wo[T_ * 512];
    __shared__ float bo[T_];
    int tid = threadIdx.x;
    for (int i = tid; i < T_ * 512; i += 256) Wo[i] = Wout[i];
    if (tid < T_) bo[tid] = bout[tid];
    __syncthreads();

    int gtid = blockIdx.x * 256 + tid;      // 0..65535
    int m    = gtid >> 1;
    int half = gtid & 1;

    const float4* h4 = (const float4*)(g_hseq + (size_t)m * 512 + half * 256);
    const float4* w4base = (const float4*)(Wo);
    float acc[T_];
#pragma unroll
    for (int t = 0; t < T_; t++) acc[t] = 0.f;

    for (int k4 = 0; k4 < 64; k4++) {
        float4 h = h4[k4];
#pragma unroll
        for (int t = 0; t < T_; t++) {
            float4 w = w4base[t * 128 + half * 64 + k4];
            acc[t] = fmaf(h.x, w.x, fmaf(h.y, w.y, fmaf(h.z, w.z, fmaf(h.w, w.w, acc[t]))));
        }
    }
#pragma unroll
    for (int t = 0; t < T_; t++)
        acc[t] += __shfl_xor_sync(0xffffffffu, acc[t], 1);

    if (half == 0) {
#pragma unroll
        for (int t = 0; t < T_; t++)
            g_logits[(size_t)m * T_ + t] = acc[t] + bo[t];
    }
}

// ---------------------------------------------------------------------------
// Viterbi: one warp per batch. First-index argmax (strict >) matches
// jnp.argmax tie-breaking. Backpointers in smem.
// ---------------------------------------------------------------------------
__global__ __launch_bounds__(32) void viterbi_kernel(
    const float* __restrict__ trans, float* scores, float* paths)
{
    __shared__ float tr[T_ * T_];
    __shared__ float prev[T_];
    __shared__ unsigned char bps[(L_ - 1) * T_];

    int b = blockIdx.x;
    int j = threadIdx.x;

    for (int i = j; i < T_ * T_; i += 32) tr[i] = trans[i];
    if (j < T_) prev[j] = g_logits[(size_t)(b * L_) * T_ + j];
    __syncwarp();

    for (int t = 1; t < L_; t++) {
        float best = 0.f; int bp = 0;
        if (j < T_) {
            best = prev[0] + tr[j];
            bp = 0;
#pragma unroll
            for (int i = 1; i < T_; i++) {
                float v = prev[i] + tr[i * T_ + j];
                if (v > best) { best = v; bp = i; }
            }
        }
        __syncwarp();
        if (j < T_) {
            prev[j] = g_logits[(size_t)(b * L_ + t) * T_ + j] + best;
            bps[(t - 1) * T_ + j] = (unsigned char)bp;
        }
        __syncwarp();
    }

    if (j == 0) {
        float best = prev[0]; int tag = 0;
        for (int i = 1; i < T_; i++) if (prev[i] > best) { best = prev[i]; tag = i; }
        if (scores) scores[b] = best;
        if (paths) {
            paths[b * L_ + (L_ - 1)] = (float)tag;
            int st = tag;
            for (int t = L_ - 2; t >= 0; t--) {
                st = bps[t * T_ + st];
                paths[b * L_ + t] = (float)st;
            }
        }
    }
}

// ---------------------------------------------------------------------------
// Launcher
// ---------------------------------------------------------------------------
extern "C" void kernel_launch(void* const* d_in, const int* in_sizes, int n_in,
                              void* d_out, int out_size)
{
    const int*   sent  = (const int*)  d_in[0];
    const float* emb   = (const float*)d_in[1];
    const float* Wih_f = (const float*)d_in[2];
    const float* Whh_f = (const float*)d_in[3];
    const float* b_f   = (const float*)d_in[4];
    const float* Wih_b = (const float*)d_in[5];
    const float* Whh_b = (const float*)d_in[6];
    const float* b_b   = (const float*)d_in[7];
    const float* Wout  = (const float*)d_in[8];
    const float* bout  = (const float*)d_in[9];
    const float* trans = (const float*)d_in[10];
    const float* h0    = (const float*)d_in[11];
    const float* c0    = (const float*)d_in[12];

    float* out = (float*)d_out;
    float* scores = nullptr;
    float* paths  = nullptr;
    if (out_size >= B_ + B_ * L_)      { scores = out; paths = out + B_; }
    else if (out_size == B_ * L_)      { paths = out; }
    else                               { scores = out; }

    // 1. init h buffers + counters
    init_kernel<<<128, 256>>>(h0);

    // 2. fused embed + input projections (both directions)
    dim3 gg(G4H / 64, M_ / 128, 2);   // (16, 256, 2)
    input_gemm_kernel<<<gg, 256>>>(sent, emb, Wih_f, b_f, Wih_b, b_b);

    // 3. persistent recurrence (128 co-resident blocks, ~146 KB smem each)
    const int smem_bytes = (128 * 260 + 8 * 260 + 128 * 9) * (int)sizeof(float);
    cudaFuncSetAttribute(lstm_kernel, cudaFuncAttributeMaxDynamicSharedMemorySize, smem_bytes);
    lstm_kernel<<<NBLK_LSTM, 256, smem_bytes>>>(c0, Whh_f, Whh_b);

    // 4. output projection (split-k x2)
    logits_kernel<<<M_ / 128, 256>>>(Wout, bout);

    // 5. Viterbi decode + write outputs
    viterbi_kernel<<<B_, 32>>>(trans, scores, paths);
}